// round 13
// baseline (speedup 1.0000x reference)
#include <cuda_runtime.h>
#include <cuda_bf16.h>

#define BATCH 16
#define MP 30      // max people
#define NJ 17      // joints
#define AD 17      // ae tag dim
#define RES 512
#define RR (RES*RES)

#define JPI (MP * NJ)                    // 510 joints per image
#define NJT (BATCH * JPI)                // 8160 joints total
#define NPT (BATCH * MP)                 // 480 persons total
#define TOTAL_ELEMS (NJT * AD)           // 147456 gather tasks

// accumulators (zero-init; finalize kernel re-zeroes after consuming)
__device__ float g_psum[NPT * AD];       // per-(person,d) masked tag sums
__device__ float g_j1[NJT];              // per-joint sum_d v
__device__ float g_j2[NJT];              // per-joint sum_d v^2

// ---------------------------------------------------------------------------
// Kernel 1: scattered gather + RED.ADD accumulation. One thread per (joint,d).
// Invisible joints: no loads, no atomics (accumulators stay 0 => exact).
// ---------------------------------------------------------------------------
__global__ __launch_bounds__(256)
void ae_gather_kernel(const float* __restrict__ tags,
                      const int*   __restrict__ joints)
{
    const int e = blockIdx.x * blockDim.x + threadIdx.x;
    if (e >= TOTAL_ELEMS) return;

    const int d  = e % AD;
    const int jj = e / AD;               // global joint id [0, NJT)
    const int b  = jj / JPI;
    const int pt = jj / NJ;              // global person id [0, NPT)

    const int idx = __ldg(&joints[jj * 2 + 0]);
    const int vis = __ldg(&joints[jj * 2 + 1]);

    if (vis > 0) {
        int off = idx % RR;
        if (off < 0) off += RR;
        const int x = off % RES;         // first spatial axis (torch convention)
        const int y = off / RES;
        const float v = __ldg(tags + (size_t)b * AD * RR + (size_t)d * RR
                                   + (size_t)x * RES + y);
        atomicAdd(&g_psum[pt * AD + d], v);   // RED (no return use)
        atomicAdd(&g_j1[jj], v);
        atomicAdd(&g_j2[jj], v * v);
    }
}

// ---------------------------------------------------------------------------
// Kernel 2: finalize per image (16 CTAs), then zero the accumulators.
// ---------------------------------------------------------------------------
__global__ __launch_bounds__(512, 1)
void ae_final_kernel(const int* __restrict__ joints,
                     float*     __restrict__ out)
{
    const int b   = blockIdx.x;
    const int tid = threadIdx.x;
    const unsigned FULL = 0xffffffffu;

    __shared__ float sh_cnt[MP];
    __shared__ float sh_sq[MP];
    __shared__ float cntv[MP];
    __shared__ float pv[MP];
    __shared__ float mean_s[MP][AD];
    __shared__ float ntags_s;
    __shared__ float push_acc;

    if (tid < MP) { sh_cnt[tid] = 0.0f; sh_sq[tid] = 0.0f; }
    if (tid == 0) push_acc = 0.0f;
    __syncthreads();

    // ---- per-joint: valid count + sq_j = 2*D*j2 - 2*j1^2 (masked => exact 0) ----
    float j1v = 0.0f, j2v = 0.0f, psv = 0.0f;   // stash for zeroing later
    if (tid < JPI) {
        const int jg = b * JPI + tid;            // global joint id
        const int m  = tid / NJ;
        const float valid = (__ldg(&joints[jg * 2 + 1]) > 0) ? 1.0f : 0.0f;
        j1v = g_j1[jg];
        j2v = g_j2[jg];
        psv = g_psum[b * JPI + tid];             // image's psum slab is 510 floats
        const float sq_j = 2.0f * (float)AD * j2v - 2.0f * j1v * j1v;
        atomicAdd(&sh_cnt[m], valid);
        atomicAdd(&sh_sq[m],  sq_j);
    }
    __syncthreads();

    if (tid < MP) {
        const float c = sh_cnt[tid];
        cntv[tid] = c;
        pv[tid]   = (c > 0.0f) ? 1.0f : 0.0f;
    }
    __syncthreads();

    // ---- means: tid < 510 == MP*AD exactly ----
    if (tid < MP * AD) {
        const int m = tid / AD;
        mean_s[m][tid % AD] = psv / fmaxf(cntv[m], 1.0f);
    }

    // ---- n_tags + pull on warp 0 ----
    if (tid < 32) {
        float nt = 0.0f, pl = 0.0f;
        if (tid < MP) {
            nt = pv[tid];
            pl = pv[tid] * sh_sq[tid] / ((float)(AD * AD) * fmaxf(cntv[tid], 1.0f));
        }
        #pragma unroll
        for (int o = 16; o > 0; o >>= 1) {
            nt += __shfl_down_sync(FULL, nt, o);
            pl += __shfl_down_sync(FULL, pl, o);
        }
        if (tid == 0) {
            ntags_s = nt;
            out[BATCH + b] = pl / fmaxf(nt, 1.0f);   // pull[16]
        }
    }

    // ---- zero this image's accumulator slabs for the next graph replay ----
    // (safe: values already captured in j1v/j2v/psv + shared above)
    if (tid < JPI) {
        const int jg = b * JPI + tid;
        g_j1[jg] = 0.0f;
        g_j2[jg] = 0.0f;
        g_psum[b * JPI + tid] = 0.0f;
    }
    __syncthreads();

    // ---- push: 900 ordered pairs (diagonal included), 2 per thread ----
    float acc = 0.0f;
    #pragma unroll
    for (int p = tid; p < MP * MP; p += 512) {
        const int m1 = p / MP;
        const int m2 = p % MP;
        const float w = pv[m1] * pv[m2];
        if (w != 0.0f) {
            float s = 0.0f;
            #pragma unroll
            for (int d = 0; d < AD; d++) {
                float df = mean_s[m1][d] - mean_s[m2][d];
                s += __expf(-df * df);
            }
            acc += s * (1.0f / (float)AD);
        }
    }
    #pragma unroll
    for (int o = 16; o > 0; o >>= 1)
        acc += __shfl_down_sync(FULL, acc, o);
    if ((tid & 31) == 0) atomicAdd(&push_acc, acc);
    __syncthreads();

    if (tid == 0) {
        const float nt = ntags_s;
        const float denom = fmaxf(nt, 1.0f);
        out[b] = (nt >= 2.0f) ? (push_acc / (denom * denom)) : 0.0f;  // push[16]
    }
}

extern "C" void kernel_launch(void* const* d_in, const int* in_sizes, int n_in,
                              void* d_out, int out_size)
{
    const float* tags   = (const float*)d_in[0];
    const int*   joints = (const int*)d_in[1];
    float*       out    = (float*)d_out;

    const int threads = 256;
    const int blocks  = (TOTAL_ELEMS + threads - 1) / threads;  // 576
    ae_gather_kernel<<<blocks, threads>>>(tags, joints);
    ae_final_kernel<<<BATCH, 512>>>(joints, out);
}

// round 14
// speedup vs baseline: 1.2113x; 1.2113x over previous
#include <cuda_runtime.h>
#include <cuda_bf16.h>

#define BATCH 16
#define MP 30      // max people
#define NJ 17      // joints
#define AD 17      // ae tag dim
#define RES 512
#define RR (RES*RES)

#define JPI   (MP * NJ)                 // 510 joints per image
#define ROWP  20                        // padded floats per joint row (80B)
#define TOTAL_ELEMS (BATCH * JPI * AD)  // 147456 gather tasks
#define NPAIR 435                       // MP*(MP-1)/2 unordered pairs

// scratch: masked gathered tags, padded rows: [b*JPI + jl][ROWP]
__device__ __align__(16) float g_scratch[BATCH * JPI * ROWP];

// ---------------------------------------------------------------------------
// Kernel 1: scattered gather, one thread per (b,m,j,d)  [measured-best shape]
// ---------------------------------------------------------------------------
__global__ __launch_bounds__(256)
void ae_gather_kernel(const float* __restrict__ tags,
                      const int*   __restrict__ joints)
{
    int e = blockIdx.x * blockDim.x + threadIdx.x;
    if (e >= TOTAL_ELEMS) return;

    const int d  = e % AD;
    const int jj = e / AD;               // global joint id in [0, B*JPI)
    const int b  = jj / JPI;

    const int idx = __ldg(&joints[jj * 2 + 0]);
    const int vis = __ldg(&joints[jj * 2 + 1]);

    float v = 0.0f;
    if (vis > 0) {
        int off = idx % RR;
        if (off < 0) off += RR;
        const int x = off % RES;         // first spatial axis (torch convention)
        const int y = off / RES;
        v = __ldg(tags + (size_t)b * AD * RR + (size_t)d * RR
                       + (size_t)x * RES + y);
    }
    g_scratch[(size_t)jj * ROWP + d] = v;
}

// ---------------------------------------------------------------------------
// Kernel 2: per-image reduction — lean cycle path.
// ---------------------------------------------------------------------------
__global__ __launch_bounds__(512, 1)
void ae_reduce_kernel(const int* __restrict__ joints,
                      float*     __restrict__ out)
{
    const int b   = blockIdx.x;
    const int tid = threadIdx.x;
    const unsigned FULL = 0xffffffffu;

    __shared__ float sqj[JPI];          // per-joint 2D*s2-2*s1^2 (auto-0 if invalid)
    __shared__ float validv[JPI];
    __shared__ float rcnt[MP];          // 1 / safe_cnt
    __shared__ float cntv[MP];
    __shared__ float pv[MP];
    __shared__ float sqp[MP];
    __shared__ float mean_s[MP][AD];
    __shared__ float ntags_s;
    __shared__ float push_acc;

    if (tid == 0) push_acc = 0.0f;

    const float* sc_b = g_scratch + ((size_t)b * JPI) * ROWP;

    // ---- phase 1: per-joint s1/s2 from padded scratch rows (vec loads) ----
    if (tid < JPI) {
        const float4* p4 = (const float4*)(sc_b + (size_t)tid * ROWP);
        float4 r0 = __ldg(p4 + 0);
        float4 r1 = __ldg(p4 + 1);
        float4 r2 = __ldg(p4 + 2);
        float4 r3 = __ldg(p4 + 3);
        float  rl = __ldg((const float*)(p4 + 4));

        float s1 = r0.x + r0.y + r0.z + r0.w
                 + r1.x + r1.y + r1.z + r1.w
                 + r2.x + r2.y + r2.z + r2.w
                 + r3.x + r3.y + r3.z + r3.w + rl;
        float s2 = r0.x*r0.x + r0.y*r0.y + r0.z*r0.z + r0.w*r0.w
                 + r1.x*r1.x + r1.y*r1.y + r1.z*r1.z + r1.w*r1.w
                 + r2.x*r2.x + r2.y*r2.y + r2.z*r2.z + r2.w*r2.w
                 + r3.x*r3.x + r3.y*r3.y + r3.z*r3.z + r3.w*r3.w + rl*rl;

        // masked values => exact 0 for invisible joints
        sqj[tid]    = 2.0f * (float)AD * s2 - 2.0f * s1 * s1;
        validv[tid] = (__ldg(&joints[(b * JPI + tid) * 2 + 1]) > 0) ? 1.0f : 0.0f;
    }
    __syncthreads();

    // ---- phase 2: per-person cnt/sq + ONE reciprocal each ----
    if (tid < MP) {
        float cnt = 0.0f, sq = 0.0f;
        #pragma unroll
        for (int j = 0; j < NJ; j++) {
            cnt += validv[tid * NJ + j];
            sq  += sqj[tid * NJ + j];
        }
        cntv[tid] = cnt;
        sqp[tid]  = sq;
        pv[tid]   = (cnt > 0.0f) ? 1.0f : 0.0f;
        rcnt[tid] = 1.0f / fmaxf(cnt, 1.0f);
    }
    __syncthreads();

    // ---- phase 3a: means via L1-hot scratch re-reads, multiply by rcnt ----
    if (tid < MP * AD) {
        const int m = tid / AD;
        const int d = tid % AD;
        const float* col = sc_b + (size_t)m * NJ * ROWP + d;
        float s = 0.0f;
        #pragma unroll
        for (int j = 0; j < NJ; j++) s += __ldg(col + j * ROWP);
        mean_s[m][d] = s * rcnt[m];
    }

    // ---- phase 3b: n_tags + pull on warp 0 (independent of 3a) ----
    if (tid < 32) {
        float nt = 0.0f, pl = 0.0f;
        if (tid < MP) {
            nt = pv[tid];
            pl = pv[tid] * sqp[tid] * rcnt[tid] * (1.0f / (float)(AD * AD));
        }
        #pragma unroll
        for (int o = 16; o > 0; o >>= 1) {
            nt += __shfl_down_sync(FULL, nt, o);
            pl += __shfl_down_sync(FULL, pl, o);
        }
        if (tid == 0) {
            ntags_s = nt;
            out[BATCH + b] = pl / fmaxf(nt, 1.0f);   // pull[16]
        }
    }
    __syncthreads();

    // ---- phase 4: 435 unordered pairs, closed-form decode, 17 EX2 each ----
    float acc = 0.0f;
    if (tid < NPAIR) {
        const int p = tid;
        // invert p = m1*(2*MP-1-m1)/2 + (m2-m1-1)
        float disc = (float)((2 * MP - 1) * (2 * MP - 1)) - 8.0f * (float)p;
        int m1 = (int)floorf(((float)(2 * MP - 1) - sqrtf(disc)) * 0.5f);
        // clamp against float rounding (at most one step)
        if ((m1 + 1) * (2 * MP - 2 - m1) / 2 <= p) m1++;
        if (m1 * (2 * MP - 1 - m1) / 2 > p)        m1--;
        const int m2 = m1 + 1 + (p - m1 * (2 * MP - 1 - m1) / 2);

        if (pv[m1] * pv[m2] != 0.0f) {
            float s = 0.0f;
            #pragma unroll
            for (int d = 0; d < AD; d++) {
                float df = mean_s[m1][d] - mean_s[m2][d];
                s += __expf(-df * df);
            }
            acc = s * (1.0f / (float)AD);
        }
    }
    #pragma unroll
    for (int o = 16; o > 0; o >>= 1)
        acc += __shfl_down_sync(FULL, acc, o);
    if ((tid & 31) == 0 && tid < NPAIR) atomicAdd(&push_acc, acc);
    __syncthreads();

    if (tid == 0) {
        const float nt = ntags_s;
        const float denom = fmaxf(nt, 1.0f);
        // ordered off-diag = 2 * unordered; diagonal sum = nt (exp(0)=1)
        out[b] = (nt >= 2.0f) ? ((2.0f * push_acc + nt) / (denom * denom)) : 0.0f;
    }
}

extern "C" void kernel_launch(void* const* d_in, const int* in_sizes, int n_in,
                              void* d_out, int out_size)
{
    const float* tags   = (const float*)d_in[0];
    const int*   joints = (const int*)d_in[1];
    float*       out    = (float*)d_out;

    const int threads = 256;
    const int blocks  = (TOTAL_ELEMS + threads - 1) / threads;  // 576
    ae_gather_kernel<<<blocks, threads>>>(tags, joints);
    ae_reduce_kernel<<<BATCH, 512>>>(joints, out);
}